// round 8
// baseline (speedup 1.0000x reference)
#include <cuda_runtime.h>
#include <cstdint>

#define N_NODES 50000
#define N_EDGES 800000
#define D 256
#define BN_EPS 1e-5f

// ---------------- scratch (device globals: allocation-free) ----------------
__device__ int   g_cnt[N_NODES];        // in-degree (without self loop)
__device__ int   g_fill[N_NODES];       // CSR fill cursors
__device__ int   g_off[N_NODES];        // CSR offsets (exclusive scan of cnt)
__device__ int   g_csr_src[N_EDGES];    // edge sources grouped by destination
__device__ float g_dinv[N_NODES];
__device__ float g_hprime[(size_t)N_NODES * D];   // dinv[i] * (x[i] @ W^T)
__device__ float g_agg[(size_t)N_NODES * D];      // aggregated (+bias) result
__device__ float g_sum[D];
__device__ float g_sumsq[D];
__device__ float g_scale[D];
__device__ float g_shift[D];

// ---------------- 1) init counters + BN sums ----------------
__global__ void init_kernel() {
    int i = blockIdx.x * blockDim.x + threadIdx.x;
    if (i < N_NODES) { g_cnt[i] = 0; g_fill[i] = 0; }
    if (i < D) { g_sum[i] = 0.0f; g_sumsq[i] = 0.0f; }
}

// ---------------- 2) in-degree count over edge targets (int32 indices!) ----
__global__ void count_kernel(const int* __restrict__ col) {
    int e = blockIdx.x * blockDim.x + threadIdx.x;
    if (e < N_EDGES) atomicAdd(&g_cnt[col[e]], 1);
}

// ---------------- 3) dinv = rsqrt(deg); deg = cnt + 1 (self loop) ---------
__global__ void dinv_kernel() {
    int i = blockIdx.x * blockDim.x + threadIdx.x;
    if (i < N_NODES) g_dinv[i] = rsqrtf((float)(g_cnt[i] + 1));
}

// ---------------- 4) exclusive scan of cnt -> off (single block) ----------
__global__ void __launch_bounds__(1024) scan_kernel() {
    __shared__ int sm[1024];
    const int tid = threadIdx.x;
    const int chunk = (N_NODES + 1023) / 1024;   // 49
    const int start = tid * chunk;

    int local = 0;
    for (int i = 0; i < chunk; i++) {
        int idx = start + i;
        if (idx < N_NODES) local += g_cnt[idx];
    }
    sm[tid] = local;
    __syncthreads();
    // Hillis-Steele inclusive scan
    for (int ofs = 1; ofs < 1024; ofs <<= 1) {
        int v = (tid >= ofs) ? sm[tid - ofs] : 0;
        __syncthreads();
        sm[tid] += v;
        __syncthreads();
    }
    int running = sm[tid] - local;               // exclusive prefix
    for (int i = 0; i < chunk; i++) {
        int idx = start + i;
        if (idx < N_NODES) {
            g_off[idx] = running;
            running += g_cnt[idx];
        }
    }
}

// ---------------- 5) fill CSR: group edge sources by destination ----------
__global__ void fill_kernel(const int* __restrict__ row,
                            const int* __restrict__ col) {
    int e = blockIdx.x * blockDim.x + threadIdx.x;
    if (e >= N_EDGES) return;
    int src = row[e];
    int dst = col[e];
    int pos = g_off[dst] + atomicAdd(&g_fill[dst], 1);
    g_csr_src[pos] = src;
}

// ---------------- 6) SGEMM h' = dinv .* (x @ W^T) ----------
// BM=128, BN=128, BK=8, TM=TN=8, 256 threads.
__global__ void __launch_bounds__(256) gemm_kernel(const float* __restrict__ x,
                                                   const float* __restrict__ W) {
    __shared__ float As[8][128];
    __shared__ float Bs[8][128];
    const int brow = blockIdx.x * 128;
    const int bcol = blockIdx.y * 128;
    const int tid  = threadIdx.x;
    const int tx   = tid & 15;
    const int ty   = tid >> 4;
    const int lrow = tid >> 1;          // 0..127
    const int lcol = (tid & 1) * 4;     // 0 or 4

    float acc[8][8];
#pragma unroll
    for (int i = 0; i < 8; i++)
#pragma unroll
        for (int j = 0; j < 8; j++) acc[i][j] = 0.0f;

    const int  arow   = brow + lrow;
    const bool avalid = (arow < N_NODES);
    const float* xa = x + (size_t)arow * D + lcol;
    const float* wb = W + (size_t)(bcol + lrow) * D + lcol;

    for (int k0 = 0; k0 < D; k0 += 8) {
        float4 av = avalid ? *reinterpret_cast<const float4*>(xa + k0)
                           : make_float4(0.f, 0.f, 0.f, 0.f);
        float4 bv = *reinterpret_cast<const float4*>(wb + k0);
        As[lcol + 0][lrow] = av.x; As[lcol + 1][lrow] = av.y;
        As[lcol + 2][lrow] = av.z; As[lcol + 3][lrow] = av.w;
        Bs[lcol + 0][lrow] = bv.x; Bs[lcol + 1][lrow] = bv.y;
        Bs[lcol + 2][lrow] = bv.z; Bs[lcol + 3][lrow] = bv.w;
        __syncthreads();
#pragma unroll
        for (int k = 0; k < 8; k++) {
            float4 a0 = *reinterpret_cast<const float4*>(&As[k][ty * 8]);
            float4 a1 = *reinterpret_cast<const float4*>(&As[k][ty * 8 + 4]);
            float4 b0 = *reinterpret_cast<const float4*>(&Bs[k][tx * 8]);
            float4 b1 = *reinterpret_cast<const float4*>(&Bs[k][tx * 8 + 4]);
            float a[8] = {a0.x, a0.y, a0.z, a0.w, a1.x, a1.y, a1.z, a1.w};
            float b[8] = {b0.x, b0.y, b0.z, b0.w, b1.x, b1.y, b1.z, b1.w};
#pragma unroll
            for (int i = 0; i < 8; i++)
#pragma unroll
                for (int j = 0; j < 8; j++)
                    acc[i][j] = fmaf(a[i], b[j], acc[i][j]);
        }
        __syncthreads();
    }

#pragma unroll
    for (int i = 0; i < 8; i++) {
        int gr = brow + ty * 8 + i;
        if (gr >= N_NODES) continue;
        float  dv   = g_dinv[gr];
        size_t base = (size_t)gr * D + bcol + tx * 8;
#pragma unroll
        for (int j = 0; j < 8; j += 4) {
            float4 v = make_float4(acc[i][j] * dv, acc[i][j + 1] * dv,
                                   acc[i][j + 2] * dv, acc[i][j + 3] * dv);
            *reinterpret_cast<float4*>(g_hprime + base + j) = v;
        }
    }
}

// ---------------- 7) gather-aggregate: one warp per node ----------
// agg[c] = dinv[c] * ( h'[c] + sum_{src in N(c)} h'[src] ) + bias
__device__ __forceinline__ void acc4(float4& a, const float4& b) {
    a.x += b.x; a.y += b.y; a.z += b.z; a.w += b.w;
}

__global__ void __launch_bounds__(256) aggregate_kernel(const float* __restrict__ bias) {
    const int warp = (blockIdx.x * blockDim.x + threadIdx.x) >> 5;
    const int lane = threadIdx.x & 31;
    if (warp >= N_NODES) return;
    const int c = warp;

    const float4* hp4 = reinterpret_cast<const float4*>(g_hprime);
    // self-loop contribution
    float4 a0 = hp4[(size_t)c * 64 + lane];
    float4 a1 = hp4[(size_t)c * 64 + lane + 32];
    float4 e0 = make_float4(0.f, 0.f, 0.f, 0.f);
    float4 e1 = make_float4(0.f, 0.f, 0.f, 0.f);

    const int beg = g_off[c];
    const int end = beg + g_cnt[c];
    int e = beg;
    for (; e + 1 < end; e += 2) {
        int s0 = g_csr_src[e];
        int s1 = g_csr_src[e + 1];
        const float4* p0 = hp4 + (size_t)s0 * 64;
        const float4* p1 = hp4 + (size_t)s1 * 64;
        float4 u0 = p0[lane], u1 = p0[lane + 32];
        float4 w0 = p1[lane], w1 = p1[lane + 32];
        acc4(a0, u0); acc4(a1, u1);
        acc4(e0, w0); acc4(e1, w1);
    }
    if (e < end) {
        int s0 = g_csr_src[e];
        const float4* p0 = hp4 + (size_t)s0 * 64;
        acc4(a0, p0[lane]); acc4(a1, p0[lane + 32]);
    }
    acc4(a0, e0); acc4(a1, e1);

    const float dv = g_dinv[c];
    const float4* b4 = reinterpret_cast<const float4*>(bias);
    float4 bb0 = b4[lane], bb1 = b4[lane + 32];
    a0.x = fmaf(a0.x, dv, bb0.x); a0.y = fmaf(a0.y, dv, bb0.y);
    a0.z = fmaf(a0.z, dv, bb0.z); a0.w = fmaf(a0.w, dv, bb0.w);
    a1.x = fmaf(a1.x, dv, bb1.x); a1.y = fmaf(a1.y, dv, bb1.y);
    a1.z = fmaf(a1.z, dv, bb1.z); a1.w = fmaf(a1.w, dv, bb1.w);

    float4* out4 = reinterpret_cast<float4*>(g_agg);
    out4[(size_t)c * 64 + lane]      = a0;
    out4[(size_t)c * 64 + lane + 32] = a1;
}

// ---------------- 8) per-column sums for BN ----------
__global__ void colsum_kernel() {
    int t  = threadIdx.x;                 // column 0..255
    int r0 = blockIdx.x * 128;
    int r1 = min(r0 + 128, N_NODES);
    float s = 0.0f, s2 = 0.0f;
    for (int r = r0; r < r1; r++) {
        float v = g_agg[(size_t)r * D + t];
        s  += v;
        s2 += v * v;
    }
    atomicAdd(&g_sum[t], s);
    atomicAdd(&g_sumsq[t], s2);
}

// ---------------- 9) BN affine params ----------
__global__ void bn_params_kernel(const float* __restrict__ gamma,
                                 const float* __restrict__ beta) {
    int t = threadIdx.x;
    float invN = 1.0f / (float)N_NODES;
    float mean = g_sum[t] * invN;
    float var  = g_sumsq[t] * invN - mean * mean;
    float sc   = gamma[t] * rsqrtf(var + BN_EPS);
    g_scale[t] = sc;
    g_shift[t] = beta[t] - mean * sc;
}

// ---------------- 10) y = relu(agg*scale + shift) ----------
__global__ void output_kernel(float* __restrict__ out) {
    int i = blockIdx.x * blockDim.x + threadIdx.x;       // float4 index
    const int total4 = N_NODES * D / 4;
    if (i >= total4) return;
    int c = (i & 63) * 4;
    float4 v  = reinterpret_cast<const float4*>(g_agg)[i];
    float4 sc = *reinterpret_cast<const float4*>(g_scale + c);
    float4 sh = *reinterpret_cast<const float4*>(g_shift + c);
    float4 y;
    y.x = fmaxf(fmaf(v.x, sc.x, sh.x), 0.0f);
    y.y = fmaxf(fmaf(v.y, sc.y, sh.y), 0.0f);
    y.z = fmaxf(fmaf(v.z, sc.z, sh.z), 0.0f);
    y.w = fmaxf(fmaf(v.w, sc.w, sh.w), 0.0f);
    reinterpret_cast<float4*>(out)[i] = y;
}

// ---------------- launch ----------------
extern "C" void kernel_launch(void* const* d_in, const int* in_sizes, int n_in,
                              void* d_out, int out_size) {
    const float* x     = (const float*)d_in[0];
    const int*   ei    = (const int*)d_in[1];     // int32! (JAX x64 disabled)
    const float* W     = (const float*)d_in[2];
    const float* bias  = (const float*)d_in[3];
    const float* gamma = (const float*)d_in[4];
    const float* beta  = (const float*)d_in[5];
    const int*   row   = ei;              // sources
    const int*   col   = ei + N_EDGES;    // targets
    float* out = (float*)d_out;

    init_kernel<<<(N_NODES + 255) / 256, 256>>>();
    count_kernel<<<(N_EDGES + 255) / 256, 256>>>(col);
    dinv_kernel<<<(N_NODES + 255) / 256, 256>>>();
    scan_kernel<<<1, 1024>>>();
    fill_kernel<<<(N_EDGES + 255) / 256, 256>>>(row, col);

    dim3 gemm_grid((N_NODES + 127) / 128, D / 128);
    gemm_kernel<<<gemm_grid, 256>>>(x, W);

    aggregate_kernel<<<(N_NODES * 32 + 255) / 256, 256>>>(bias);

    colsum_kernel<<<(N_NODES + 127) / 128, 256>>>();
    bn_params_kernel<<<1, 256>>>(gamma, beta);
    output_kernel<<<(N_NODES * D / 4 + 255) / 256, 256>>>(out);
}

// round 9
// speedup vs baseline: 1.1252x; 1.1252x over previous
#include <cuda_runtime.h>
#include <cstdint>

#define N_NODES 50000
#define N_EDGES 800000
#define D 256
#define BN_EPS 1e-5f
#define SCAN_NB 196            // ceil(50000/256)

// ---------------- scratch (device globals: allocation-free) ----------------
__device__ int   g_cnt[N_NODES];        // in-degree (without self loop)
__device__ int   g_fill[N_NODES];       // CSR fill cursors
__device__ int   g_off[N_NODES];        // CSR offsets (exclusive scan of cnt)
__device__ int   g_csr_src[N_EDGES];    // edge sources grouped by destination
__device__ float g_dinv[N_NODES];
__device__ int   g_part[256];           // per-block partial sums (scan)
__device__ int   g_partpref[256];       // exclusive prefix of partials
__device__ float g_hprime[(size_t)N_NODES * D];   // dinv[i] * (x[i] @ W^T)
__device__ float g_agg[(size_t)N_NODES * D];      // aggregated (+bias) result
__device__ float g_sum[D];
__device__ float g_sumsq[D];
__device__ float g_scale[D];
__device__ float g_shift[D];

// ---------------- 1) init counters + BN sums ----------------
__global__ void init_kernel() {
    int i = blockIdx.x * blockDim.x + threadIdx.x;
    if (i < N_NODES) { g_cnt[i] = 0; g_fill[i] = 0; }
    if (i < D) { g_sum[i] = 0.0f; g_sumsq[i] = 0.0f; }
}

// ---------------- 2) in-degree count over edge targets (int32 indices) ----
__global__ void count_kernel(const int* __restrict__ col) {
    int e = blockIdx.x * blockDim.x + threadIdx.x;
    if (e < N_EDGES) atomicAdd(&g_cnt[col[e]], 1);
}

// ---------------- 3a) per-block sums of cnt ----------------
__global__ void __launch_bounds__(256) blocksum_kernel() {
    const int tid  = threadIdx.x;
    const int lane = tid & 31;
    const int wid  = tid >> 5;
    int i = blockIdx.x * 256 + tid;
    int v = (i < N_NODES) ? g_cnt[i] : 0;
#pragma unroll
    for (int ofs = 16; ofs > 0; ofs >>= 1)
        v += __shfl_down_sync(0xffffffffu, v, ofs);
    __shared__ int ws[8];
    if (lane == 0) ws[wid] = v;
    __syncthreads();
    if (tid == 0) {
        int s = 0;
#pragma unroll
        for (int w = 0; w < 8; w++) s += ws[w];
        g_part[blockIdx.x] = s;
    }
}

// ---------------- 3b) exclusive scan of 196 partials (1 block) ------------
__global__ void __launch_bounds__(256) partscan_kernel() {
    __shared__ int sm[256];
    const int tid = threadIdx.x;
    int v = (tid < SCAN_NB) ? g_part[tid] : 0;
    sm[tid] = v;
    __syncthreads();
#pragma unroll
    for (int ofs = 1; ofs < 256; ofs <<= 1) {
        int t = (tid >= ofs) ? sm[tid - ofs] : 0;
        __syncthreads();
        sm[tid] += t;
        __syncthreads();
    }
    if (tid < SCAN_NB) g_partpref[tid] = sm[tid] - v;   // exclusive
}

// ---------------- 3c) per-block exclusive scan + prefix, and dinv ---------
__global__ void __launch_bounds__(256) offsets_kernel() {
    __shared__ int sm[256];
    const int tid = threadIdx.x;
    int i = blockIdx.x * 256 + tid;
    int v = (i < N_NODES) ? g_cnt[i] : 0;
    sm[tid] = v;
    __syncthreads();
#pragma unroll
    for (int ofs = 1; ofs < 256; ofs <<= 1) {
        int t = (tid >= ofs) ? sm[tid - ofs] : 0;
        __syncthreads();
        sm[tid] += t;
        __syncthreads();
    }
    if (i < N_NODES) {
        g_off[i]  = sm[tid] - v + g_partpref[blockIdx.x];
        g_dinv[i] = rsqrtf((float)(v + 1));
    }
}

// ---------------- 4) fill CSR: group edge sources by destination ----------
__global__ void fill_kernel(const int* __restrict__ row,
                            const int* __restrict__ col) {
    int e = blockIdx.x * blockDim.x + threadIdx.x;
    if (e >= N_EDGES) return;
    int src = row[e];
    int dst = col[e];
    int pos = g_off[dst] + atomicAdd(&g_fill[dst], 1);
    g_csr_src[pos] = src;
}

// ---------------- 5) SGEMM h' = dinv .* (x @ W^T), double-buffered --------
// BM=128, BN=128, BK=8, TM=TN=8, 256 threads.
__global__ void __launch_bounds__(256) gemm_kernel(const float* __restrict__ x,
                                                   const float* __restrict__ W) {
    __shared__ float As[2][8][128];
    __shared__ float Bs[2][8][128];
    const int brow = blockIdx.x * 128;
    const int bcol = blockIdx.y * 128;
    const int tid  = threadIdx.x;
    const int tx   = tid & 15;
    const int ty   = tid >> 4;
    const int lrow = tid >> 1;          // 0..127
    const int lcol = (tid & 1) * 4;     // 0 or 4

    float acc[8][8];
#pragma unroll
    for (int i = 0; i < 8; i++)
#pragma unroll
        for (int j = 0; j < 8; j++) acc[i][j] = 0.0f;

    const int  arow   = brow + lrow;
    const bool avalid = (arow < N_NODES);
    const float* xa = x + (size_t)arow * D + lcol;
    const float* wb = W + (size_t)(bcol + lrow) * D + lcol;

    // preload k0 = 0 into buffer 0
    {
        float4 av = avalid ? *reinterpret_cast<const float4*>(xa)
                           : make_float4(0.f, 0.f, 0.f, 0.f);
        float4 bv = *reinterpret_cast<const float4*>(wb);
        As[0][lcol + 0][lrow] = av.x; As[0][lcol + 1][lrow] = av.y;
        As[0][lcol + 2][lrow] = av.z; As[0][lcol + 3][lrow] = av.w;
        Bs[0][lcol + 0][lrow] = bv.x; Bs[0][lcol + 1][lrow] = bv.y;
        Bs[0][lcol + 2][lrow] = bv.z; Bs[0][lcol + 3][lrow] = bv.w;
    }
    __syncthreads();

    int buf = 0;
    for (int k0 = 0; k0 < D; k0 += 8) {
        float4 nav, nbv;
        const bool more = (k0 + 8 < D);
        if (more) {
            nav = avalid ? *reinterpret_cast<const float4*>(xa + k0 + 8)
                         : make_float4(0.f, 0.f, 0.f, 0.f);
            nbv = *reinterpret_cast<const float4*>(wb + k0 + 8);
        }
#pragma unroll
        for (int k = 0; k < 8; k++) {
            float4 a0 = *reinterpret_cast<const float4*>(&As[buf][k][ty * 8]);
            float4 a1 = *reinterpret_cast<const float4*>(&As[buf][k][ty * 8 + 4]);
            float4 b0 = *reinterpret_cast<const float4*>(&Bs[buf][k][tx * 8]);
            float4 b1 = *reinterpret_cast<const float4*>(&Bs[buf][k][tx * 8 + 4]);
            float a[8] = {a0.x, a0.y, a0.z, a0.w, a1.x, a1.y, a1.z, a1.w};
            float b[8] = {b0.x, b0.y, b0.z, b0.w, b1.x, b1.y, b1.z, b1.w};
#pragma unroll
            for (int i = 0; i < 8; i++)
#pragma unroll
                for (int j = 0; j < 8; j++)
                    acc[i][j] = fmaf(a[i], b[j], acc[i][j]);
        }
        if (more) {
            int nb = buf ^ 1;
            As[nb][lcol + 0][lrow] = nav.x; As[nb][lcol + 1][lrow] = nav.y;
            As[nb][lcol + 2][lrow] = nav.z; As[nb][lcol + 3][lrow] = nav.w;
            Bs[nb][lcol + 0][lrow] = nbv.x; Bs[nb][lcol + 1][lrow] = nbv.y;
            Bs[nb][lcol + 2][lrow] = nbv.z; Bs[nb][lcol + 3][lrow] = nbv.w;
            __syncthreads();
            buf = nb;
        }
    }

#pragma unroll
    for (int i = 0; i < 8; i++) {
        int gr = brow + ty * 8 + i;
        if (gr >= N_NODES) continue;
        float  dv   = g_dinv[gr];
        size_t base = (size_t)gr * D + bcol + tx * 8;
#pragma unroll
        for (int j = 0; j < 8; j += 4) {
            float4 v = make_float4(acc[i][j] * dv, acc[i][j + 1] * dv,
                                   acc[i][j + 2] * dv, acc[i][j + 3] * dv);
            *reinterpret_cast<float4*>(g_hprime + base + j) = v;
        }
    }
}

// ---------------- 6) gather-aggregate + fused BN column stats -------------
// agg[c] = dinv[c] * ( h'[c] + sum_{src in N(c)} h'[src] ) + bias
// one warp per node, grid-stride; per-thread column sum/sumsq accumulators.
__device__ __forceinline__ void acc4(float4& a, const float4& b) {
    a.x += b.x; a.y += b.y; a.z += b.z; a.w += b.w;
}

__global__ void __launch_bounds__(256) aggregate_kernel(const float* __restrict__ bias) {
    __shared__ float s_sum[D];
    __shared__ float s_sq[D];
    const int tid  = threadIdx.x;
    const int lane = tid & 31;
    const int wid  = tid >> 5;
    s_sum[tid] = 0.0f;
    s_sq[tid]  = 0.0f;
    __syncthreads();

    const float4* hp4 = reinterpret_cast<const float4*>(g_hprime);
    float4*       out4 = reinterpret_cast<float4*>(g_agg);
    const float4* b4   = reinterpret_cast<const float4*>(bias);
    const float4 bb0 = b4[lane];
    const float4 bb1 = b4[lane + 32];

    float4 ts0 = make_float4(0.f, 0.f, 0.f, 0.f);   // sums, cols 4*lane..+3
    float4 ts1 = make_float4(0.f, 0.f, 0.f, 0.f);   // sums, cols 128+4*lane..+3
    float4 tq0 = make_float4(0.f, 0.f, 0.f, 0.f);   // sumsq
    float4 tq1 = make_float4(0.f, 0.f, 0.f, 0.f);

    const int warp0  = blockIdx.x * 8 + wid;
    const int nwarps = gridDim.x * 8;

    for (int c = warp0; c < N_NODES; c += nwarps) {
        // self-loop contribution
        float4 a0 = hp4[(size_t)c * 64 + lane];
        float4 a1 = hp4[(size_t)c * 64 + lane + 32];
        float4 e0 = make_float4(0.f, 0.f, 0.f, 0.f);
        float4 e1 = make_float4(0.f, 0.f, 0.f, 0.f);

        const int beg = g_off[c];
        const int end = beg + g_cnt[c];
        int e = beg;
        for (; e + 1 < end; e += 2) {
            int s0 = g_csr_src[e];
            int s1 = g_csr_src[e + 1];
            const float4* p0 = hp4 + (size_t)s0 * 64;
            const float4* p1 = hp4 + (size_t)s1 * 64;
            float4 u0 = p0[lane], u1 = p0[lane + 32];
            float4 w0 = p1[lane], w1 = p1[lane + 32];
            acc4(a0, u0); acc4(a1, u1);
            acc4(e0, w0); acc4(e1, w1);
        }
        if (e < end) {
            int s0 = g_csr_src[e];
            const float4* p0 = hp4 + (size_t)s0 * 64;
            acc4(a0, p0[lane]); acc4(a1, p0[lane + 32]);
        }
        acc4(a0, e0); acc4(a1, e1);

        const float dv = g_dinv[c];
        a0.x = fmaf(a0.x, dv, bb0.x); a0.y = fmaf(a0.y, dv, bb0.y);
        a0.z = fmaf(a0.z, dv, bb0.z); a0.w = fmaf(a0.w, dv, bb0.w);
        a1.x = fmaf(a1.x, dv, bb1.x); a1.y = fmaf(a1.y, dv, bb1.y);
        a1.z = fmaf(a1.z, dv, bb1.z); a1.w = fmaf(a1.w, dv, bb1.w);

        out4[(size_t)c * 64 + lane]      = a0;
        out4[(size_t)c * 64 + lane + 32] = a1;

        acc4(ts0, a0); acc4(ts1, a1);
        tq0.x = fmaf(a0.x, a0.x, tq0.x); tq0.y = fmaf(a0.y, a0.y, tq0.y);
        tq0.z = fmaf(a0.z, a0.z, tq0.z); tq0.w = fmaf(a0.w, a0.w, tq0.w);
        tq1.x = fmaf(a1.x, a1.x, tq1.x); tq1.y = fmaf(a1.y, a1.y, tq1.y);
        tq1.z = fmaf(a1.z, a1.z, tq1.z); tq1.w = fmaf(a1.w, a1.w, tq1.w);
    }

    // block-level reduce into shared (8-way conflict across warps: cheap)
    const int c0 = 4 * lane;
    atomicAdd(&s_sum[c0 + 0], ts0.x); atomicAdd(&s_sum[c0 + 1], ts0.y);
    atomicAdd(&s_sum[c0 + 2], ts0.z); atomicAdd(&s_sum[c0 + 3], ts0.w);
    atomicAdd(&s_sum[128 + c0 + 0], ts1.x); atomicAdd(&s_sum[128 + c0 + 1], ts1.y);
    atomicAdd(&s_sum[128 + c0 + 2], ts1.z); atomicAdd(&s_sum[128 + c0 + 3], ts1.w);
    atomicAdd(&s_sq[c0 + 0], tq0.x); atomicAdd(&s_sq[c0 + 1], tq0.y);
    atomicAdd(&s_sq[c0 + 2], tq0.z); atomicAdd(&s_sq[c0 + 3], tq0.w);
    atomicAdd(&s_sq[128 + c0 + 0], tq1.x); atomicAdd(&s_sq[128 + c0 + 1], tq1.y);
    atomicAdd(&s_sq[128 + c0 + 2], tq1.z); atomicAdd(&s_sq[128 + c0 + 3], tq1.w);
    __syncthreads();

    atomicAdd(&g_sum[tid],   s_sum[tid]);
    atomicAdd(&g_sumsq[tid], s_sq[tid]);
}

// ---------------- 7) BN affine params ----------
__global__ void bn_params_kernel(const float* __restrict__ gamma,
                                 const float* __restrict__ beta) {
    int t = threadIdx.x;
    float invN = 1.0f / (float)N_NODES;
    float mean = g_sum[t] * invN;
    float var  = g_sumsq[t] * invN - mean * mean;
    float sc   = gamma[t] * rsqrtf(var + BN_EPS);
    g_scale[t] = sc;
    g_shift[t] = beta[t] - mean * sc;
}

// ---------------- 8) y = relu(agg*scale + shift) ----------
__global__ void output_kernel(float* __restrict__ out) {
    int i = blockIdx.x * blockDim.x + threadIdx.x;       // float4 index
    const int total4 = N_NODES * D / 4;
    if (i >= total4) return;
    int c = (i & 63) * 4;
    float4 v  = reinterpret_cast<const float4*>(g_agg)[i];
    float4 sc = *reinterpret_cast<const float4*>(g_scale + c);
    float4 sh = *reinterpret_cast<const float4*>(g_shift + c);
    float4 y;
    y.x = fmaxf(fmaf(v.x, sc.x, sh.x), 0.0f);
    y.y = fmaxf(fmaf(v.y, sc.y, sh.y), 0.0f);
    y.z = fmaxf(fmaf(v.z, sc.z, sh.z), 0.0f);
    y.w = fmaxf(fmaf(v.w, sc.w, sh.w), 0.0f);
    reinterpret_cast<float4*>(out)[i] = y;
}

// ---------------- launch ----------------
extern "C" void kernel_launch(void* const* d_in, const int* in_sizes, int n_in,
                              void* d_out, int out_size) {
    const float* x     = (const float*)d_in[0];
    const int*   ei    = (const int*)d_in[1];     // int32 (JAX x64 disabled)
    const float* W     = (const float*)d_in[2];
    const float* bias  = (const float*)d_in[3];
    const float* gamma = (const float*)d_in[4];
    const float* beta  = (const float*)d_in[5];
    const int*   row   = ei;              // sources
    const int*   col   = ei + N_EDGES;    // targets
    float* out = (float*)d_out;

    init_kernel<<<(N_NODES + 255) / 256, 256>>>();
    count_kernel<<<(N_EDGES + 255) / 256, 256>>>(col);
    blocksum_kernel<<<SCAN_NB, 256>>>();
    partscan_kernel<<<1, 256>>>();
    offsets_kernel<<<SCAN_NB, 256>>>();
    fill_kernel<<<(N_EDGES + 255) / 256, 256>>>(row, col);

    dim3 gemm_grid((N_NODES + 127) / 128, D / 128);
    gemm_kernel<<<gemm_grid, 256>>>(x, W);

    aggregate_kernel<<<592, 256>>>(bias);

    bn_params_kernel<<<1, 256>>>(gamma, beta);
    output_kernel<<<(N_NODES * D / 4 + 255) / 256, 256>>>(out);
}